// round 16
// baseline (speedup 1.0000x reference)
#include <cuda_runtime.h>
#include <cuda_fp16.h>
#include <cstdint>

#define IN_DIM 128
#define OUT_DIM 64
#define MAXN 50000
#define MAXE 1600000
#define SLOPE 0.1f
#define EPS 1e-12f
#define SCAN_BLK 1024
#define MAX_SCAN_BLOCKS 64

// smem plan for k_transform (floats):
//  xs[128][132] | wt[128][65] | us[128] | ud[128] | sas[64] | sad[64] | sb[64] | ba[2]
#define OFF_XS 0
#define OFF_WT 16896
#define OFF_US 25216
#define OFF_UD 25344
#define OFF_SAS 25472
#define OFF_SAD 25536
#define OFF_SB 25600
#define OFF_BA 25664
#define SMEM_FLOATS 25666
#define SMEM_BYTES (SMEM_FLOATS * 4)

// Scratch (static device globals — allocation is forbidden). Zero-init at load.
__device__ __align__(256) __half g_newh[MAXN * OUT_DIM]; // transformed features, fp16
__device__ float  g_ssrc[MAXN];          // new[n] . a_src  (exact fp32 via u-projection)
__device__ float  g_sdst[MAXN];          // new[n] . a_dst
__device__ int    g_cnt[MAXN];           // out-degree histogram (zeroed by k_aggregate)
__device__ int    g_base[MAXN];          // CSR offsets (mutated by k_place into end[])
__device__ int    g_csr[MAXE];           // src-sorted dst indices (4B payload)
__device__ int    g_bsum[MAX_SCAN_BLOCKS];
__device__ int    g_flag[MAX_SCAN_BLOCKS];

__device__ __forceinline__ uint32_t f2tf32(float f) {
    uint32_t u;
    asm("cvt.rna.tf32.f32 %0, %1;" : "=r"(u) : "f"(f));
    return u;
}

// ---------------------------------------------------------------------------
// Kernel A (stream A): transform new = x@W^T + b -> fp16 via tf32 tensor-core
// mma.sync m16n8k8. 256 threads = 8 warps; block tile = 128 nodes.
// Scores computed EXACTLY in fp32 via s = x·(W^T a) + b·a (independent of the
// tf32 GEMM error). xs padded to 132 floats/row and wt to 65/row for
// conflict-free fragment LDS.
// ---------------------------------------------------------------------------
__global__ __launch_bounds__(256) void k_transform(
    const float* __restrict__ x, const float* __restrict__ W,
    const float* __restrict__ b, const float* __restrict__ a, int nN)
{
    extern __shared__ float sm[];
    float* xs  = sm + OFF_XS;    // [128][132]
    float* wt  = sm + OFF_WT;    // [128][65]  wt[k][d] = W[d][k]
    float* us  = sm + OFF_US;
    float* ud  = sm + OFF_UD;
    float* sas = sm + OFF_SAS;
    float* sad = sm + OFF_SAD;
    float* sb  = sm + OFF_SB;
    float* ba  = sm + OFF_BA;

    int tid  = threadIdx.x;
    int base = blockIdx.x * 128;

    // stage W transposed (read coalesced, write conflict-free: bank=(k+d)%32)
    for (int i = tid; i < OUT_DIM * IN_DIM; i += 256) {
        int d = i >> 7, k = i & 127;
        wt[k * 65 + d] = W[i];
    }
    if (tid < OUT_DIM) {
        sas[tid] = a[tid];
        sad[tid] = a[OUT_DIM + tid];
        sb[tid]  = b[tid];
    }
    // stage x tile coalesced (float4); zero-fill tail rows
    for (int i = tid; i < 128 * 32; i += 256) {
        int r = i >> 5, q = i & 31;
        int gr = base + r;
        float4 v = (gr < nN) ? ((const float4*)x)[(size_t)gr * 32 + q]
                             : make_float4(0.f, 0.f, 0.f, 0.f);
        *(float4*)&xs[r * 132 + q * 4] = v;
    }
    __syncthreads();

    // u = W^T a (per k), and b·a scalars
    if (tid < 128) {
        float accs = 0.f, accd = 0.f;
        const float* wr = &wt[tid * 65];
#pragma unroll 8
        for (int d = 0; d < OUT_DIM; d++) {
            float w = wr[d];
            accs += w * sas[d];
            accd += w * sad[d];
        }
        us[tid] = accs;
        ud[tid] = accd;
    } else if (tid == 128) {
        float s1 = 0.f, s2 = 0.f;
        for (int d = 0; d < OUT_DIM; d++) { s1 += sb[d] * sas[d]; s2 += sb[d] * sad[d]; }
        ba[0] = s1; ba[1] = s2;
    }
    __syncthreads();

    // exact fp32 scores: 2 threads per node (halves of k), combined via shfl
    {
        int n = tid >> 1, h = tid & 1;
        const float* xr  = &xs[n * 132 + h * 64];
        const float* usr = &us[h * 64];
        const float* udr = &ud[h * 64];
        float acc_s = 0.f, acc_d = 0.f;
#pragma unroll 8
        for (int k = 0; k < 64; k++) {
            float xv = xr[k];
            acc_s += xv * usr[k];
            acc_d += xv * udr[k];
        }
        acc_s += __shfl_xor_sync(0xFFFFFFFF, acc_s, 1);
        acc_d += __shfl_xor_sync(0xFFFFFFFF, acc_d, 1);
        int gn = base + n;
        if (h == 0 && gn < nN) {
            g_ssrc[gn] = acc_s + ba[0];
            g_sdst[gn] = acc_d + ba[1];
        }
    }

    // ---- tf32 MMA: warp w owns nodes [base + w*16, +16), all 64 out dims ----
    int wid = tid >> 5, lane = tid & 31;
    int g = lane >> 2, t = lane & 3;
    int rb = wid * 16;

    float c[8][4];
#pragma unroll
    for (int nf = 0; nf < 8; nf++)
#pragma unroll
        for (int j = 0; j < 4; j++) c[nf][j] = 0.f;

    for (int k0 = 0; k0 < IN_DIM; k0 += 8) {
        // A fragment (m16k8, row-major): a0=(g,t) a1=(g+8,t) a2=(g,t+4) a3=(g+8,t+4)
        uint32_t a0 = f2tf32(xs[(rb + g) * 132 + k0 + t]);
        uint32_t a1 = f2tf32(xs[(rb + g + 8) * 132 + k0 + t]);
        uint32_t a2 = f2tf32(xs[(rb + g) * 132 + k0 + t + 4]);
        uint32_t a3 = f2tf32(xs[(rb + g + 8) * 132 + k0 + t + 4]);
#pragma unroll
        for (int nf = 0; nf < 8; nf++) {
            // B fragment (k8n8, col-major): b0=B[t][g], b1=B[t+4][g]; B[k][n]=wt[k][nf*8+n]
            uint32_t b0 = f2tf32(wt[(k0 + t) * 65 + nf * 8 + g]);
            uint32_t b1 = f2tf32(wt[(k0 + t + 4) * 65 + nf * 8 + g]);
            asm volatile(
                "mma.sync.aligned.m16n8k8.row.col.f32.tf32.tf32.f32 "
                "{%0,%1,%2,%3},{%4,%5,%6,%7},{%8,%9},{%0,%1,%2,%3};"
                : "+f"(c[nf][0]), "+f"(c[nf][1]), "+f"(c[nf][2]), "+f"(c[nf][3])
                : "r"(a0), "r"(a1), "r"(a2), "r"(a3), "r"(b0), "r"(b1));
        }
    }

    // epilogue: +bias, fp16, store. C layout: c0=(g,2t) c1=(g,2t+1) c2=(g+8,2t) c3=(g+8,2t+1)
    int row0 = base + rb + g;
#pragma unroll
    for (int nf = 0; nf < 8; nf++) {
        int col = nf * 8 + 2 * t;
        float bb0 = sb[col], bb1 = sb[col + 1];
        if (row0 < nN) {
            __half2 h01 = __floats2half2_rn(c[nf][0] + bb0, c[nf][1] + bb1);
            *(__half2*)&g_newh[(size_t)row0 * OUT_DIM + col] = h01;
        }
        if (row0 + 8 < nN) {
            __half2 h23 = __floats2half2_rn(c[nf][2] + bb0, c[nf][3] + bb1);
            *(__half2*)&g_newh[(size_t)(row0 + 8) * OUT_DIM + col] = h23;
        }
    }
}

// ---------------------------------------------------------------------------
// Kernel 1 (main stream): histogram of src; block 0 zeroes scan flags first.
// ---------------------------------------------------------------------------
__global__ __launch_bounds__(256) void k_hist(
    const int* __restrict__ eidx, int nE, int nN)
{
    if (blockIdx.x == 0 && threadIdx.x < MAX_SCAN_BLOCKS) g_flag[threadIdx.x] = 0;
    int e = blockIdx.x * blockDim.x + threadIdx.x;
    if (e >= nE) return;
    int s = eidx[e];
    s = min(max(s, 0), nN - 1);
    atomicAdd(&g_cnt[s], 1);
}

// ---------------------------------------------------------------------------
// Kernel 2: exclusive scan of g_cnt -> g_base, decoupled lookback.
// ---------------------------------------------------------------------------
__global__ __launch_bounds__(SCAN_BLK) void k_scan(int nN)
{
    __shared__ int swarp[32];
    __shared__ int s_total;
    __shared__ int s_boff;
    int tid  = threadIdx.x;
    int lane = tid & 31;
    int wid  = tid >> 5;
    int bid  = blockIdx.x;
    int i    = bid * SCAN_BLK + tid;

    int v = (i < nN) ? g_cnt[i] : 0;

    int inc = v;
#pragma unroll
    for (int off = 1; off < 32; off <<= 1) {
        int t = __shfl_up_sync(0xFFFFFFFF, inc, off);
        if (lane >= off) inc += t;
    }
    if (lane == 31) swarp[wid] = inc;
    __syncthreads();
    if (wid == 0) {
        int wv = swarp[lane];
        int winc = wv;
#pragma unroll
        for (int off = 1; off < 32; off <<= 1) {
            int t = __shfl_up_sync(0xFFFFFFFF, winc, off);
            if (lane >= off) winc += t;
        }
        swarp[lane] = winc - wv;
    }
    __syncthreads();
    int incl = swarp[wid] + inc;
    if (tid == SCAN_BLK - 1) s_total = incl;
    __syncthreads();

    if (tid == 0) {
        g_bsum[bid] = s_total;
        __threadfence();
        *(volatile int*)&g_flag[bid] = 1;
    }

    if (wid == 0) {
        int off = 0;
        for (int base = 0; base < bid; base += 32) {
            int j = base + lane;
            int vj = 0;
            if (j < bid) {
                while (*(volatile int*)&g_flag[j] == 0) {}
                __threadfence();
                vj = *(volatile int*)&g_bsum[j];
            }
#pragma unroll
            for (int o = 16; o > 0; o >>= 1)
                vj += __shfl_down_sync(0xFFFFFFFF, vj, o);
            off += __shfl_sync(0xFFFFFFFF, vj, 0);
        }
        if (lane == 0) s_boff = off;
    }
    __syncthreads();

    if (i < nN) g_base[i] = s_boff + incl - v;
}

// ---------------------------------------------------------------------------
// Kernel 3: place dst (4B) into CSR slot. Cursor atomic leaves g_base[n]==end.
// ---------------------------------------------------------------------------
__global__ __launch_bounds__(256) void k_place(
    const int* __restrict__ eidx, int nE, int nN)
{
    int e = blockIdx.x * blockDim.x + threadIdx.x;
    if (e >= nE) return;
    int s = eidx[e];
    int d = eidx[(size_t)nE + e];
    s = min(max(s, 0), nN - 1);
    d = min(max(d, 0), nN - 1);
    int pos = atomicAdd(&g_base[s], 1);
    g_csr[pos] = d;
}

// ---------------------------------------------------------------------------
// Kernel 4: gather-aggregate + normalize (verified R10 form). 8 lanes/node,
// lane c owns 16B of the fp16 row; score/exp recomputed per warp-inst;
// unrolled x4 for MLP. Re-zeroes g_cnt for replay.
// ---------------------------------------------------------------------------
__global__ __launch_bounds__(256) void k_aggregate(
    float* __restrict__ out, int nN)
{
    int n = blockIdx.x * 32 + (threadIdx.x >> 3);
    int c = threadIdx.x & 7;
    if (n >= nN) return;

    int beg = (n == 0) ? 0 : g_base[n - 1];
    int end = g_base[n];
    float ssn = g_ssrc[n];

    float acc[8];
#pragma unroll
    for (int j = 0; j < 8; j++) acc[j] = 0.f;
    float rs = 0.f;

    int i = beg;
    for (; i + 4 <= end; i += 4) {
        int dst0 = g_csr[i];
        int dst1 = g_csr[i + 1];
        int dst2 = g_csr[i + 2];
        int dst3 = g_csr[i + 3];
        float sd0 = g_sdst[dst0];
        float sd1 = g_sdst[dst1];
        float sd2 = g_sdst[dst2];
        float sd3 = g_sdst[dst3];
        uint4 h0 = *(const uint4*)(g_newh + ((size_t)dst0 << 6) + c * 8);
        uint4 h1 = *(const uint4*)(g_newh + ((size_t)dst1 << 6) + c * 8);
        uint4 h2 = *(const uint4*)(g_newh + ((size_t)dst2 << 6) + c * 8);
        uint4 h3 = *(const uint4*)(g_newh + ((size_t)dst3 << 6) + c * 8);
        float sc0 = ssn + sd0;  sc0 = sc0 > 0.f ? sc0 : SLOPE * sc0;
        float sc1 = ssn + sd1;  sc1 = sc1 > 0.f ? sc1 : SLOPE * sc1;
        float sc2 = ssn + sd2;  sc2 = sc2 > 0.f ? sc2 : SLOPE * sc2;
        float sc3 = ssn + sd3;  sc3 = sc3 > 0.f ? sc3 : SLOPE * sc3;
        float ev0 = __expf(sc0);
        float ev1 = __expf(sc1);
        float ev2 = __expf(sc2);
        float ev3 = __expf(sc3);
#pragma unroll
        for (int q = 0; q < 4; q++) {
            float ev = (q == 0) ? ev0 : (q == 1) ? ev1 : (q == 2) ? ev2 : ev3;
            uint4 hv = (q == 0) ? h0 : (q == 1) ? h1 : (q == 2) ? h2 : h3;
            float2 f0 = __half22float2(*(__half2*)&hv.x);
            float2 f1 = __half22float2(*(__half2*)&hv.y);
            float2 f2 = __half22float2(*(__half2*)&hv.z);
            float2 f3 = __half22float2(*(__half2*)&hv.w);
            acc[0] += ev * f0.x;  acc[1] += ev * f0.y;
            acc[2] += ev * f1.x;  acc[3] += ev * f1.y;
            acc[4] += ev * f2.x;  acc[5] += ev * f2.y;
            acc[6] += ev * f3.x;  acc[7] += ev * f3.y;
            rs += ev;
        }
    }
    for (; i < end; i++) {
        int dst = g_csr[i];
        float sc = ssn + g_sdst[dst];
        sc = sc > 0.f ? sc : SLOPE * sc;
        float ev = __expf(sc);
        uint4 hv = *(const uint4*)(g_newh + ((size_t)dst << 6) + c * 8);
        float2 f0 = __half22float2(*(__half2*)&hv.x);
        float2 f1 = __half22float2(*(__half2*)&hv.y);
        float2 f2 = __half22float2(*(__half2*)&hv.z);
        float2 f3 = __half22float2(*(__half2*)&hv.w);
        acc[0] += ev * f0.x;  acc[1] += ev * f0.y;
        acc[2] += ev * f1.x;  acc[3] += ev * f1.y;
        acc[4] += ev * f2.x;  acc[5] += ev * f2.y;
        acc[6] += ev * f3.x;  acc[7] += ev * f3.y;
        rs += ev;
    }

    float inv = 1.f / (rs + EPS);
    float* op = out + ((size_t)n << 6) + c * 8;
    *(float4*)op       = make_float4(acc[0]*inv, acc[1]*inv, acc[2]*inv, acc[3]*inv);
    *(float4*)(op + 4) = make_float4(acc[4]*inv, acc[5]*inv, acc[6]*inv, acc[7]*inv);

    if (c == 0) g_cnt[n] = 0;   // clean for next launch (graph replay)
}

// ---------------------------------------------------------------------------
// Topology: transform (tensor-core, ~9us) forks onto sA and hides under hist;
// main chain hist -> scan -> place; join before aggregate.
// ---------------------------------------------------------------------------
extern "C" void kernel_launch(void* const* d_in, const int* in_sizes, int n_in,
                              void* d_out, int out_size)
{
    const float* x    = (const float*)d_in[0];
    const int*   eidx = (const int*)d_in[1];    // int32 (JAX x64 disabled)
    const float* W    = (const float*)d_in[2];
    const float* b    = (const float*)d_in[3];
    const float* a    = (const float*)d_in[4];
    float* out = (float*)d_out;

    int nN = in_sizes[0] / IN_DIM;   // 50000
    int nE = in_sizes[1] / 2;        // 1600000

    static cudaStream_t sA = nullptr;
    static cudaEvent_t  e0 = nullptr, eA = nullptr;
    if (sA == nullptr) {
        cudaStreamCreateWithFlags(&sA, cudaStreamNonBlocking);
        cudaEventCreateWithFlags(&e0, cudaEventDisableTiming);
        cudaEventCreateWithFlags(&eA, cudaEventDisableTiming);
        cudaFuncSetAttribute(k_transform,
                             cudaFuncAttributeMaxDynamicSharedMemorySize,
                             SMEM_BYTES);
    }

    // fork: transform on sA
    cudaEventRecord(e0, 0);
    cudaStreamWaitEvent(sA, e0, 0);
    int nbX = (nN + 127) / 128;
    k_transform<<<nbX, 256, SMEM_BYTES, sA>>>(x, W, b, a, nN);
    cudaEventRecord(eA, sA);

    // main chain: hist -> scan -> place
    k_hist<<<(nE + 255) / 256, 256>>>(eidx, nE, nN);
    int nbS = (nN + SCAN_BLK - 1) / SCAN_BLK;     // 49
    k_scan<<<nbS, SCAN_BLK>>>(nN);
    k_place<<<(nE + 255) / 256, 256>>>(eidx, nE, nN);

    // join: aggregate needs transform outputs too
    cudaStreamWaitEvent(0, eA, 0);
    k_aggregate<<<(nN + 31) / 32, 256>>>(out, nN);
}

// round 17
// speedup vs baseline: 1.0945x; 1.0945x over previous
#include <cuda_runtime.h>
#include <cuda_fp16.h>
#include <cstdint>

#define IN_DIM 128
#define OUT_DIM 64
#define MAXN 50000
#define MAXE 1600000
#define SLOPE 0.1f
#define EPS 1e-12f
#define SCAN_BLK 1024
#define MAX_SCAN_BLOCKS 64

// Scratch (static device globals — allocation is forbidden). Zero-init at load.
__device__ __align__(256) __half g_newh[MAXN * OUT_DIM]; // transformed features, fp16
__device__ float  g_ssrc[MAXN];          // new[n] . a_src
__device__ float  g_sdst[MAXN];          // new[n] . a_dst
__device__ int    g_cnt[MAXN];           // out-degree histogram (zeroed by k_aggregate)
__device__ int    g_base[MAXN];          // CSR offsets (mutated by k_place into end[])
__device__ int    g_csr[MAXE];           // src-sorted dst indices (4B payload)
__device__ int    g_bsum[MAX_SCAN_BLOCKS];
__device__ int    g_flag[MAX_SCAN_BLOCKS];

// ---------------------------------------------------------------------------
// Kernel A (stream A): transform new = x@W^T+b -> fp16, scores.
// Proven R4/R15 form: one node/thread, warp-uniform W broadcast from smem.
// Runs concurrently with the hist->scan->place chain.
// ---------------------------------------------------------------------------
__global__ __launch_bounds__(256) void k_transform(
    const float* __restrict__ x, const float* __restrict__ W,
    const float* __restrict__ b, const float* __restrict__ a, int nN)
{
    __shared__ __align__(16) float sW[OUT_DIM * IN_DIM];
    __shared__ float sb[OUT_DIM], sas[OUT_DIM], sad[OUT_DIM];
    for (int i = threadIdx.x; i < OUT_DIM * IN_DIM; i += blockDim.x) sW[i] = W[i];
    if (threadIdx.x < OUT_DIM) {
        sb[threadIdx.x]  = b[threadIdx.x];
        sas[threadIdx.x] = a[threadIdx.x];
        sad[threadIdx.x] = a[OUT_DIM + threadIdx.x];
    }
    __syncthreads();

    int n = blockIdx.x * blockDim.x + threadIdx.x;
    if (n >= nN) return;

    const float4* __restrict__ x4 = (const float4*)(x + (size_t)n * IN_DIM);
    const float4* __restrict__ W4 = (const float4*)sW;

    float acc[OUT_DIM];
#pragma unroll
    for (int d = 0; d < OUT_DIM; d++) acc[d] = 0.f;

    for (int kk = 0; kk < IN_DIM / 4; kk++) {
        float4 xv = x4[kk];
#pragma unroll
        for (int d = 0; d < OUT_DIM; d++) {
            float4 wv = W4[d * (IN_DIM / 4) + kk];   // warp-uniform broadcast
            acc[d] += xv.x * wv.x + xv.y * wv.y + xv.z * wv.z + xv.w * wv.w;
        }
    }

    float ss = 0.f, sd = 0.f;
    uint2* newh = (uint2*)(g_newh + ((size_t)n << 6));
#pragma unroll
    for (int j = 0; j < OUT_DIM / 4; j++) {
        float v0 = acc[4*j+0] + sb[4*j+0];
        float v1 = acc[4*j+1] + sb[4*j+1];
        float v2 = acc[4*j+2] + sb[4*j+2];
        float v3 = acc[4*j+3] + sb[4*j+3];
        __half2 h0 = __float22half2_rn(make_float2(v0, v1));
        __half2 h1 = __float22half2_rn(make_float2(v2, v3));
        uint2 hv;
        hv.x = *(unsigned int*)&h0;
        hv.y = *(unsigned int*)&h1;
        newh[j] = hv;
        ss += v0*sas[4*j+0] + v1*sas[4*j+1] + v2*sas[4*j+2] + v3*sas[4*j+3];
        sd += v0*sad[4*j+0] + v1*sad[4*j+1] + v2*sad[4*j+2] + v3*sad[4*j+3];
    }
    g_ssrc[n] = ss;
    g_sdst[n] = sd;
}

// ---------------------------------------------------------------------------
// Kernel 1 (main stream): histogram of src; block 0 zeroes scan flags first.
// ---------------------------------------------------------------------------
__global__ __launch_bounds__(256) void k_hist(
    const int* __restrict__ eidx, int nE, int nN)
{
    if (blockIdx.x == 0 && threadIdx.x < MAX_SCAN_BLOCKS) g_flag[threadIdx.x] = 0;
    int e = blockIdx.x * blockDim.x + threadIdx.x;
    if (e >= nE) return;
    int s = eidx[e];
    s = min(max(s, 0), nN - 1);
    atomicAdd(&g_cnt[s], 1);
}

// ---------------------------------------------------------------------------
// Kernel 2: exclusive scan of g_cnt -> g_base, decoupled lookback.
// ---------------------------------------------------------------------------
__global__ __launch_bounds__(SCAN_BLK) void k_scan(int nN)
{
    __shared__ int swarp[32];
    __shared__ int s_total;
    __shared__ int s_boff;
    int tid  = threadIdx.x;
    int lane = tid & 31;
    int wid  = tid >> 5;
    int bid  = blockIdx.x;
    int i    = bid * SCAN_BLK + tid;

    int v = (i < nN) ? g_cnt[i] : 0;

    int inc = v;
#pragma unroll
    for (int off = 1; off < 32; off <<= 1) {
        int t = __shfl_up_sync(0xFFFFFFFF, inc, off);
        if (lane >= off) inc += t;
    }
    if (lane == 31) swarp[wid] = inc;
    __syncthreads();
    if (wid == 0) {
        int wv = swarp[lane];
        int winc = wv;
#pragma unroll
        for (int off = 1; off < 32; off <<= 1) {
            int t = __shfl_up_sync(0xFFFFFFFF, winc, off);
            if (lane >= off) winc += t;
        }
        swarp[lane] = winc - wv;
    }
    __syncthreads();
    int incl = swarp[wid] + inc;
    if (tid == SCAN_BLK - 1) s_total = incl;
    __syncthreads();

    if (tid == 0) {
        g_bsum[bid] = s_total;
        __threadfence();
        *(volatile int*)&g_flag[bid] = 1;
    }

    if (wid == 0) {
        int off = 0;
        for (int base = 0; base < bid; base += 32) {
            int j = base + lane;
            int vj = 0;
            if (j < bid) {
                while (*(volatile int*)&g_flag[j] == 0) {}
                __threadfence();
                vj = *(volatile int*)&g_bsum[j];
            }
#pragma unroll
            for (int o = 16; o > 0; o >>= 1)
                vj += __shfl_down_sync(0xFFFFFFFF, vj, o);
            off += __shfl_sync(0xFFFFFFFF, vj, 0);
        }
        if (lane == 0) s_boff = off;
    }
    __syncthreads();

    if (i < nN) g_base[i] = s_boff + incl - v;
}

// ---------------------------------------------------------------------------
// Kernel 3: place dst (4B) into CSR slot. Cursor atomic leaves g_base[n]==end.
// ---------------------------------------------------------------------------
__global__ __launch_bounds__(256) void k_place(
    const int* __restrict__ eidx, int nE, int nN)
{
    int e = blockIdx.x * blockDim.x + threadIdx.x;
    if (e >= nE) return;
    int s = eidx[e];
    int d = eidx[(size_t)nE + e];
    s = min(max(s, 0), nN - 1);
    d = min(max(d, 0), nN - 1);
    int pos = atomicAdd(&g_base[s], 1);
    g_csr[pos] = d;
}

// ---------------------------------------------------------------------------
// Kernel 4: gather-aggregate + normalize. ONE WARP PER NODE: lane = (edge
// slot e4 in 0..3, chunk c in 0..7). The edge loop is warp-uniform (i += 4),
// eliminating the ~30% issue waste from per-group degree divergence in the
// old 4-nodes-per-warp mapping. 4 gathers in flight per warp preserved.
// Final reduction across the 4 edge subgroups via shfl_xor(8) + shfl_xor(16).
// Re-zeroes g_cnt for replay.
// ---------------------------------------------------------------------------
__global__ __launch_bounds__(256) void k_aggregate(
    float* __restrict__ out, int nN)
{
    int n = (blockIdx.x * blockDim.x + threadIdx.x) >> 5;   // node = warp id
    if (n >= nN) return;
    int lane = threadIdx.x & 31;
    int e4   = lane >> 3;       // edge slot 0..3
    int c    = lane & 7;        // chunk 0..7 (8 halves each)

    int beg = (n == 0) ? 0 : g_base[n - 1];
    int end = g_base[n];
    float ssn = g_ssrc[n];

    float acc[8];
#pragma unroll
    for (int j = 0; j < 8; j++) acc[j] = 0.f;
    float rs = 0.f;

    for (int i = beg; i < end; i += 4) {        // warp-uniform loop
        int idx   = i + e4;
        bool valid = (idx < end);
        int dst   = g_csr[valid ? idx : end - 1];   // clamped: always in-bounds
        float sd  = g_sdst[dst];                    // broadcast within subgroup
        float sc  = ssn + sd;
        sc = sc > 0.f ? sc : SLOPE * sc;
        float ev  = valid ? __expf(sc) : 0.f;
        uint4 hv  = *(const uint4*)(g_newh + ((size_t)dst << 6) + c * 8);
        float2 f0 = __half22float2(*(__half2*)&hv.x);
        float2 f1 = __half22float2(*(__half2*)&hv.y);
        float2 f2 = __half22float2(*(__half2*)&hv.z);
        float2 f3 = __half22float2(*(__half2*)&hv.w);
        acc[0] += ev * f0.x;  acc[1] += ev * f0.y;
        acc[2] += ev * f1.x;  acc[3] += ev * f1.y;
        acc[4] += ev * f2.x;  acc[5] += ev * f2.y;
        acc[6] += ev * f3.x;  acc[7] += ev * f3.y;
        rs += ev;
    }

    // reduce across the 4 edge subgroups (lanes differing in bits 3,4)
#pragma unroll
    for (int j = 0; j < 8; j++) {
        acc[j] += __shfl_xor_sync(0xFFFFFFFF, acc[j], 8);
        acc[j] += __shfl_xor_sync(0xFFFFFFFF, acc[j], 16);
    }
    rs += __shfl_xor_sync(0xFFFFFFFF, rs, 8);
    rs += __shfl_xor_sync(0xFFFFFFFF, rs, 16);

    if (e4 == 0) {
        float inv = 1.f / (rs + EPS);
        float* op = out + ((size_t)n << 6) + c * 8;
        *(float4*)op       = make_float4(acc[0]*inv, acc[1]*inv, acc[2]*inv, acc[3]*inv);
        *(float4*)(op + 4) = make_float4(acc[4]*inv, acc[5]*inv, acc[6]*inv, acc[7]*inv);
        if (c == 0) g_cnt[n] = 0;   // clean for next launch (graph replay)
    }
}

// ---------------------------------------------------------------------------
// Topology (R15 winner): transform forks onto sA, overlapping the whole
// hist -> scan -> place chain; join before aggregate.
// Streams/events created once (host objects only — no device memory).
// ---------------------------------------------------------------------------
extern "C" void kernel_launch(void* const* d_in, const int* in_sizes, int n_in,
                              void* d_out, int out_size)
{
    const float* x    = (const float*)d_in[0];
    const int*   eidx = (const int*)d_in[1];    // int32 (JAX x64 disabled)
    const float* W    = (const float*)d_in[2];
    const float* b    = (const float*)d_in[3];
    const float* a    = (const float*)d_in[4];
    float* out = (float*)d_out;

    int nN = in_sizes[0] / IN_DIM;   // 50000
    int nE = in_sizes[1] / 2;        // 1600000

    static cudaStream_t sA = nullptr;
    static cudaEvent_t  e0 = nullptr, eA = nullptr;
    if (sA == nullptr) {
        cudaStreamCreateWithFlags(&sA, cudaStreamNonBlocking);
        cudaEventCreateWithFlags(&e0, cudaEventDisableTiming);
        cudaEventCreateWithFlags(&eA, cudaEventDisableTiming);
    }

    // fork: transform on sA
    cudaEventRecord(e0, 0);
    cudaStreamWaitEvent(sA, e0, 0);
    k_transform<<<(nN + 255) / 256, 256, 0, sA>>>(x, W, b, a, nN);
    cudaEventRecord(eA, sA);

    // main chain: hist -> scan -> place
    k_hist<<<(nE + 255) / 256, 256>>>(eidx, nE, nN);
    int nbS = (nN + SCAN_BLK - 1) / SCAN_BLK;     // 49
    k_scan<<<nbS, SCAN_BLK>>>(nN);
    k_place<<<(nE + 255) / 256, 256>>>(eidx, nE, nN);

    // join: aggregate needs transform outputs too
    cudaStreamWaitEvent(0, eA, 0);
    k_aggregate<<<(nN * 32 + 255) / 256, 256>>>(out, nN);
}